// round 7
// baseline (speedup 1.0000x reference)
#include <cuda_runtime.h>
#include <cuda_bf16.h>
#include <math.h>
#include <stdint.h>

// Problem constants
#define NN    16384
#define EE    131072
#define HH    256
#define LL    4
#define BB    256
#define NPG   64
#define DEG   8
#define HEADS 8
#define DK    32

// ---------------------------------------------------------------------------
// PTX helpers
// ---------------------------------------------------------------------------
static __device__ __forceinline__ uint32_t su32(const void* p) {
    uint32_t a;
    asm("{ .reg .u64 t; cvta.to.shared.u64 t, %1; cvt.u32.u64 %0, t; }"
        : "=r"(a) : "l"(p));
    return a;
}
static __device__ __forceinline__ void cp16(uint32_t s, const void* g) {
    asm volatile("cp.async.cg.shared.global [%0], [%1], 16;" :: "r"(s), "l"(g));
}
#define CP_COMMIT() asm volatile("cp.async.commit_group;")
#define CP_WAIT(n)  asm volatile("cp.async.wait_group %0;" :: "n"(n))

static __device__ __forceinline__ void ldm4(uint32_t& r0, uint32_t& r1,
                                            uint32_t& r2, uint32_t& r3, uint32_t a) {
    asm volatile("ldmatrix.sync.aligned.m8n8.x4.shared.b16 {%0,%1,%2,%3}, [%4];"
                 : "=r"(r0), "=r"(r1), "=r"(r2), "=r"(r3) : "r"(a));
}
static __device__ __forceinline__ void mma16816(float* c, const uint32_t* a,
                                                const uint32_t* b) {
    asm volatile("mma.sync.aligned.m16n8k16.row.col.f32.bf16.bf16.f32 "
                 "{%0,%1,%2,%3}, {%4,%5,%6,%7}, {%8,%9}, {%0,%1,%2,%3};"
                 : "+f"(c[0]), "+f"(c[1]), "+f"(c[2]), "+f"(c[3])
                 : "r"(a[0]), "r"(a[1]), "r"(a[2]), "r"(a[3]),
                   "r"(b[0]), "r"(b[1]));
}

// ---------------------------------------------------------------------------
// scratch
// ---------------------------------------------------------------------------
__device__ float gbuf_h   [NN * HH];
__device__ float gbuf_m   [NN * HH];
__device__ float gbuf_qkv [NN * 768];
__device__ float gbuf_att [NN * HH];
__device__ float gbuf_x   [NN * HH];
__device__ float gbuf_elog[LL * EE];
__device__ float gbuf_we  [LL * 32];
__device__ float gbuf_ce  [LL];
__device__ float gbuf_gs  [NN];
__device__ float gbuf_aip [8 * NN];
__device__ float gbuf_ajp [8 * NN];

// hi/lo bf16 planes, row-major [M,K] each (no duplication)
__device__ __nv_bfloat16 p_nf_h [NN * 64],   p_nf_l [NN * 64];
__device__ __nv_bfloat16 p_h_h  [NN * 256],  p_h_l  [NN * 256];
__device__ __nv_bfloat16 p_x_h  [NN * 256],  p_x_l  [NN * 256];
__device__ __nv_bfloat16 p_h2_h [NN * 256],  p_h2_l [NN * 256];
__device__ __nv_bfloat16 p_y1_h [NN * 512],  p_y1_l [NN * 512];
// weights transposed [N,K]
__device__ __nv_bfloat16 p_wn_h  [256 * 64],      p_wn_l  [256 * 64];
__device__ __nv_bfloat16 p_gat_h [4 * 256 * 256], p_gat_l [4 * 256 * 256];
__device__ __nv_bfloat16 p_wqkv_h[768 * 256],     p_wqkv_l[768 * 256];
__device__ __nv_bfloat16 p_w1_h  [512 * 256],     p_w1_l  [512 * 256];
__device__ __nv_bfloat16 p_w2_h  [256 * 512],     p_w2_l  [256 * 512];
__device__ __nv_bfloat16 p_gw1_h [256 * 256],     p_gw1_l [256 * 256];

static __device__ __forceinline__ void hilo(float v, __nv_bfloat16& h, __nv_bfloat16& l) {
    h = __float2bfloat16(v);
    l = __float2bfloat16(v - __bfloat162float(h));
}

// ---------------------------------------------------------------------------
// conversions
// ---------------------------------------------------------------------------
__global__ void to_hiloA(const float* __restrict__ src, long total,
                         __nv_bfloat16* __restrict__ dh, __nv_bfloat16* __restrict__ dl)
{
    long t = (long)blockIdx.x * 256 + threadIdx.x;
    if (t >= total) return;
    __nv_bfloat16 h, l;
    hilo(src[t], h, l);
    dh[t] = h; dl[t] = l;
}

struct WEnt { const float* src; __nv_bfloat16* dh; __nv_bfloat16* dl; int K; int N; };
struct WTab { WEnt e[11]; };

__global__ void conv_weights(WTab tab)
{
    WEnt w = tab.e[blockIdx.y];
    int total = w.K * w.N;
    for (int t = blockIdx.x * 256 + threadIdx.x; t < total; t += gridDim.x * 256) {
        int k = t / w.N, n = t % w.N;
        __nv_bfloat16 h, l;
        hilo(w.src[t], h, l);
        w.dh[(size_t)n * w.K + k] = h;
        w.dl[(size_t)n * w.K + k] = l;
    }
}

// ---------------------------------------------------------------------------
// HMMA GEMM: C = Ah.Bh^T + Ah.Bl^T + Al.Bh^T  (hi/lo planes, fp32 acc)
// block 128x128, 8 warps as 2(M)x4(N), warp tile 64x32, K-chunk 32, 3-stage.
// smem row (128B) = [hi 64B | lo 64B], XOR swizzle (row&7) on 16B units.
// ACT: 0 none, 1 GELU, 2 ReLU. WF32 fp32 out. WTR hi/lo planes out.
// WAL: GAT alpha partial dots into slots (bx*4+wn) of AIp/AJp [8*NN].
// ---------------------------------------------------------------------------
#define MG_SMEM 98304

template<int ACT, bool WF32, bool WTR, bool WAL>
__global__ __launch_bounds__(256)
void mma_gemm(int KC, int K,
              const __nv_bfloat16* __restrict__ Ahp, const __nv_bfloat16* __restrict__ Alp,
              const __nv_bfloat16* __restrict__ Bhp, const __nv_bfloat16* __restrict__ Blp,
              const float* __restrict__ bias, int Nout,
              float* __restrict__ C,
              __nv_bfloat16* __restrict__ Dh, __nv_bfloat16* __restrict__ Dl,
              const float* __restrict__ a_l,
              float* __restrict__ AIp, float* __restrict__ AJp)
{
    extern __shared__ char smem[];
    uint32_t sb = su32(smem);
    int tid = threadIdx.x, lane = tid & 31, wid = tid >> 5;
    int bx = blockIdx.x, by = blockIdx.y;
    const size_t abase = (size_t)by * 128 * K;
    const size_t bbase = (size_t)bx * 128 * K;

    float acc[4][4][4];
#pragma unroll
    for (int i = 0; i < 4; i++)
#pragma unroll
        for (int j = 0; j < 4; j++)
#pragma unroll
            for (int q = 0; q < 4; q++) acc[i][j][q] = 0.f;

    auto load_stage = [&](int c) {
        uint32_t st = sb + (uint32_t)(c % 3) * 32768u;
#pragma unroll
        for (int i = 0; i < 4; i++) {
            int idx = tid + i * 256;
            int row = idx >> 3, u = idx & 7;
            const __nv_bfloat16* src = (u < 4 ? Ahp : Alp) + abase
                                       + (size_t)row * K + c * 32 + (u & 3) * 8;
            cp16(st + (uint32_t)row * 128 + (uint32_t)((u ^ (row & 7)) << 4), src);
        }
#pragma unroll
        for (int i = 0; i < 4; i++) {
            int idx = tid + i * 256;
            int row = idx >> 3, u = idx & 7;
            const __nv_bfloat16* src = (u < 4 ? Bhp : Blp) + bbase
                                       + (size_t)row * K + c * 32 + (u & 3) * 8;
            cp16(st + 16384u + (uint32_t)row * 128 + (uint32_t)((u ^ (row & 7)) << 4), src);
        }
    };

    load_stage(0); CP_COMMIT();
    if (KC > 1) load_stage(1);
    CP_COMMIT();

    int wm = wid & 1, wn = wid >> 1;       // 2 M-warps x 4 N-warps
    int g = lane >> 3, r8 = lane & 7;
    int rsel = (g & 1) * 8 + r8;
    int usel = g >> 1;

    for (int c = 0; c < KC; c++) {
        CP_WAIT(1);
        __syncthreads();
        if (c + 2 < KC) load_stage(c + 2);
        CP_COMMIT();
        uint32_t as = sb + (uint32_t)(c % 3) * 32768u;
        uint32_t bs = as + 16384u;
#pragma unroll
        for (int ks = 0; ks < 2; ks++) {
            int uh = 2 * ks + usel;       // hi unit
            int ul = uh + 4;              // lo unit
            // A hi
            uint32_t ah[4][4];
#pragma unroll
            for (int mt = 0; mt < 4; mt++) {
                int row = wm * 64 + mt * 16 + rsel;
                ldm4(ah[mt][0], ah[mt][1], ah[mt][2], ah[mt][3],
                     as + (uint32_t)row * 128 + (uint32_t)((uh ^ (row & 7)) << 4));
            }
            // B hi
            uint32_t bh[4][2];
#pragma unroll
            for (int nt = 0; nt < 2; nt++) {
                int row = wn * 32 + nt * 16 + rsel;
                uint32_t r0, r1, r2, r3;
                ldm4(r0, r1, r2, r3,
                     bs + (uint32_t)row * 128 + (uint32_t)((uh ^ (row & 7)) << 4));
                bh[2 * nt][0] = r0; bh[2 * nt + 1][0] = r1;
                bh[2 * nt][1] = r2; bh[2 * nt + 1][1] = r3;
            }
#pragma unroll
            for (int mt = 0; mt < 4; mt++)
#pragma unroll
                for (int nt = 0; nt < 4; nt++)
                    mma16816(acc[mt][nt], ah[mt], bh[nt]);
            // B lo (reuse A hi regs)
            uint32_t bl[4][2];
#pragma unroll
            for (int nt = 0; nt < 2; nt++) {
                int row = wn * 32 + nt * 16 + rsel;
                uint32_t r0, r1, r2, r3;
                ldm4(r0, r1, r2, r3,
                     bs + (uint32_t)row * 128 + (uint32_t)((ul ^ (row & 7)) << 4));
                bl[2 * nt][0] = r0; bl[2 * nt + 1][0] = r1;
                bl[2 * nt][1] = r2; bl[2 * nt + 1][1] = r3;
            }
#pragma unroll
            for (int mt = 0; mt < 4; mt++)
#pragma unroll
                for (int nt = 0; nt < 4; nt++)
                    mma16816(acc[mt][nt], ah[mt], bl[nt]);
            // A lo (reuse B hi regs)
            uint32_t al[4][4];
#pragma unroll
            for (int mt = 0; mt < 4; mt++) {
                int row = wm * 64 + mt * 16 + rsel;
                ldm4(al[mt][0], al[mt][1], al[mt][2], al[mt][3],
                     as + (uint32_t)row * 128 + (uint32_t)((ul ^ (row & 7)) << 4));
            }
#pragma unroll
            for (int mt = 0; mt < 4; mt++)
#pragma unroll
                for (int nt = 0; nt < 4; nt++)
                    mma16816(acc[mt][nt], al[mt], bh[nt]);
        }
        __syncthreads();
    }

    // epilogue
    int gid = lane >> 2, qp = lane & 3;
    float sai[4][2], saj[4][2];
    if (WAL) {
#pragma unroll
        for (int i = 0; i < 4; i++)
#pragma unroll
            for (int j = 0; j < 2; j++) { sai[i][j] = 0.f; saj[i][j] = 0.f; }
    }
#pragma unroll
    for (int mt = 0; mt < 4; mt++) {
#pragma unroll
        for (int nt = 0; nt < 4; nt++) {
            int col = bx * 128 + wn * 32 + nt * 8 + qp * 2;
            float bb0 = bias ? bias[col] : 0.f;
            float bb1 = bias ? bias[col + 1] : 0.f;
#pragma unroll
            for (int hh2 = 0; hh2 < 2; hh2++) {
                long row = (long)by * 128 + wm * 64 + mt * 16 + gid + hh2 * 8;
                float v0 = acc[mt][nt][2 * hh2]     + bb0;
                float v1 = acc[mt][nt][2 * hh2 + 1] + bb1;
                if (ACT == 1) {
                    v0 = 0.5f * v0 * (1.0f + erff(v0 * 0.7071067811865475f));
                    v1 = 0.5f * v1 * (1.0f + erff(v1 * 0.7071067811865475f));
                }
                if (ACT == 2) { v0 = fmaxf(v0, 0.f); v1 = fmaxf(v1, 0.f); }
                if (WF32) {
                    float2 t2 = make_float2(v0, v1);
                    *reinterpret_cast<float2*>(&C[row * Nout + col]) = t2;
                }
                if (WAL) {
                    sai[mt][hh2] += v0 * a_l[col] + v1 * a_l[col + 1];
                    saj[mt][hh2] += v0 * a_l[HH + col] + v1 * a_l[HH + col + 1];
                }
                if (WTR) {
                    __nv_bfloat16 h0, l0, h1, l1;
                    hilo(v0, h0, l0); hilo(v1, h1, l1);
                    __nv_bfloat162 hp, lp;
                    hp.x = h0; hp.y = h1; lp.x = l0; lp.y = l1;
                    *reinterpret_cast<__nv_bfloat162*>(&Dh[row * Nout + col]) = hp;
                    *reinterpret_cast<__nv_bfloat162*>(&Dl[row * Nout + col]) = lp;
                }
            }
        }
    }
    if (WAL) {
        int slot = bx * 4 + wn;
#pragma unroll
        for (int mt = 0; mt < 4; mt++)
#pragma unroll
            for (int hh2 = 0; hh2 < 2; hh2++) {
                float si = sai[mt][hh2], sj = saj[mt][hh2];
                si += __shfl_xor_sync(0xFFFFFFFFu, si, 1);
                si += __shfl_xor_sync(0xFFFFFFFFu, si, 2);
                sj += __shfl_xor_sync(0xFFFFFFFFu, sj, 1);
                sj += __shfl_xor_sync(0xFFFFFFFFu, sj, 2);
                if (qp == 0) {
                    long row = (long)by * 128 + wm * 64 + mt * 16 + gid + hh2 * 8;
                    AIp[(size_t)slot * NN + row] = si;
                    AJp[(size_t)slot * NN + row] = sj;
                }
            }
    }
}

// ---------------------------------------------------------------------------
// fold edge weights + edge logits
// ---------------------------------------------------------------------------
__global__ void prep_kernel(const float* __restrict__ We, const float* __restrict__ be,
                            const float* __restrict__ gat_a,
                            float* __restrict__ we, float* __restrict__ ce)
{
    int tid = threadIdx.x;
    if (tid < 128) {
        int l = tid / 32, j = tid % 32;
        const float* ae = gat_a + l * 768 + 512;
        float s = 0.f;
        for (int c = 0; c < HH; c++) s += We[j * HH + c] * ae[c];
        we[tid] = s;
    } else if (tid < 132) {
        int l = tid - 128;
        const float* ae = gat_a + l * 768 + 512;
        float s = 0.f;
        for (int c = 0; c < HH; c++) s += be[c] * ae[c];
        ce[l] = s;
    }
}

__global__ void edge_logit_kernel(const float* __restrict__ ef,
                                  const float* __restrict__ we,
                                  const float* __restrict__ ce,
                                  float* __restrict__ elog)
{
    __shared__ float ws[128];
    __shared__ float cs[4];
    int tid = threadIdx.x;
    if (tid < 128) ws[tid] = we[tid];
    if (tid < 4)   cs[tid] = ce[tid];
    __syncthreads();
    int e = blockIdx.x * 256 + tid;
    float f[32];
    const float4* efp = reinterpret_cast<const float4*>(ef + (long)e * 32);
#pragma unroll
    for (int t = 0; t < 8; t++) {
        float4 x = efp[t];
        f[4*t+0] = x.x; f[4*t+1] = x.y; f[4*t+2] = x.z; f[4*t+3] = x.w;
    }
#pragma unroll
    for (int l = 0; l < LL; l++) {
        float s = cs[l];
#pragma unroll
        for (int j = 0; j < 32; j++) s += f[j] * ws[l * 32 + j];
        elog[l * EE + e] = s;
    }
}

// ---------------------------------------------------------------------------
// GAT layer (alphas precomputed by GEMM epilogue, 8 slots)
// ---------------------------------------------------------------------------
__global__ __launch_bounds__(256)
void gat_kernel(const float* __restrict__ m, float* __restrict__ h,
                const float* __restrict__ elog_l, const int* __restrict__ dst,
                const float* __restrict__ aip, const float* __restrict__ ajp,
                const float* __restrict__ lng, const float* __restrict__ lnb,
                __nv_bfloat16* __restrict__ hh_p, __nv_bfloat16* __restrict__ hl_p)
{
    int g = blockIdx.x;
    int tid = threadIdx.x;
    int w = tid >> 5, lane = tid & 31;
    __shared__ float ai[NPG], aj[NPG];
    __shared__ float s_attn[8][8];
    __shared__ int   s_dl[8][8];

    if (tid < NPG) {
        int node = g * NPG + tid;
        float si = 0.f, sj = 0.f;
#pragma unroll
        for (int s = 0; s < 8; s++) {
            si += aip[(size_t)s * NN + node];
            sj += ajp[(size_t)s * NN + node];
        }
        ai[tid] = si; aj[tid] = sj;
    }
    __syncthreads();

    for (int n = w; n < NPG; n += 8) {
        int node = g * NPG + n;
        float logit = -1e30f;
        int dl = 0;
        if (lane < DEG) {
            int e = node * DEG + lane;
            dl = dst[e] - g * NPG;
            float lg = ai[n] + aj[dl] + elog_l[e];
            logit = (lg >= 0.f) ? lg : 0.01f * lg;
        }
        float mx = logit;
#pragma unroll
        for (int o = 4; o; o >>= 1) mx = fmaxf(mx, __shfl_xor_sync(0xFFFFFFFFu, mx, o));
        float ex = (lane < DEG) ? expf(logit - mx) : 0.f;
        float sm = ex;
#pragma unroll
        for (int o = 4; o; o >>= 1) sm += __shfl_xor_sync(0xFFFFFFFFu, sm, o);
        if (lane < DEG) { s_attn[w][lane] = ex / sm; s_dl[w][lane] = dl; }
        __syncwarp();

        float acc[8];
#pragma unroll
        for (int jj = 0; jj < 8; jj++) acc[jj] = 0.f;
        long gbase = (long)g * NPG * HH;
#pragma unroll
        for (int kk = 0; kk < DEG; kk++) {
            float at = s_attn[w][kk];
            const float* mr = m + gbase + (long)s_dl[w][kk] * HH;
#pragma unroll
            for (int jj = 0; jj < 8; jj++)
                acc[jj] += at * mr[lane + 32 * jj];
        }
        float* hr = h + (long)node * HH;
        float s = 0.f, s2 = 0.f;
#pragma unroll
        for (int jj = 0; jj < 8; jj++) {
            float vv = acc[jj] + hr[lane + 32 * jj];
            acc[jj] = vv;
            s += vv; s2 += vv * vv;
        }
#pragma unroll
        for (int o = 16; o; o >>= 1) {
            s  += __shfl_xor_sync(0xFFFFFFFFu, s,  o);
            s2 += __shfl_xor_sync(0xFFFFFFFFu, s2, o);
        }
        float mean = s * (1.0f / HH);
        float var  = s2 * (1.0f / HH) - mean * mean;
        float inv  = rsqrtf(var + 1e-5f);
#pragma unroll
        for (int jj = 0; jj < 8; jj++) {
            int c = lane + 32 * jj;
            float val = (acc[jj] - mean) * inv * lng[c] + lnb[c];
            hr[c] = val;
            __nv_bfloat16 hb, lb;
            hilo(val, hb, lb);
            hh_p[(size_t)node * HH + c] = hb;
            hl_p[(size_t)node * HH + c] = lb;
        }
        __syncwarp();
    }
}

// ---------------------------------------------------------------------------
// global attention (qkv fused layout: [NN][q 256 | k 256 | v 256])
// ---------------------------------------------------------------------------
__global__ __launch_bounds__(64)
void attn_kernel(const float* __restrict__ qkv, float* __restrict__ o)
{
    int g = blockIdx.x, hd = blockIdx.y;
    int i = threadIdx.x;
    __shared__ float ks[NPG][DK];
    __shared__ float vs[NPG][DK];
    __shared__ float sc[NPG][NPG + 1];
    long nbase = (long)g * NPG;
    for (int t = i; t < NPG * DK; t += 64) {
        int r = t / DK, c = t % DK;
        long rb = (nbase + r) * 768 + hd * DK;
        ks[r][c] = qkv[rb + 256 + c];
        vs[r][c] = qkv[rb + 512 + c];
    }
    __syncthreads();
    float qr[DK];
    long qb = (nbase + i) * 768 + hd * DK;
#pragma unroll
    for (int d = 0; d < DK; d++) qr[d] = qkv[qb + d];
    float mx = -1e30f;
    for (int j = 0; j < NPG; j++) {
        float s = 0.f;
#pragma unroll
        for (int d = 0; d < DK; d++) s += qr[d] * ks[j][d];
        s *= 0.1767766952966369f;
        sc[i][j] = s;
        mx = fmaxf(mx, s);
    }
    float sm = 0.f;
    for (int j = 0; j < NPG; j++) {
        float e = expf(sc[i][j] - mx);
        sc[i][j] = e;
        sm += e;
    }
    float inv = 1.0f / sm;
    long ob = (nbase + i) * HH + hd * DK;
#pragma unroll 4
    for (int d = 0; d < DK; d++) {
        float acc = 0.f;
        for (int j = 0; j < NPG; j++) acc += sc[i][j] * vs[j][d];
        o[ob + d] = acc * inv;
    }
}

// ---------------------------------------------------------------------------
// out = LN(a + b) fp32 + optional hi/lo planes
// ---------------------------------------------------------------------------
__global__ __launch_bounds__(256)
void add_ln_kernel(const float* __restrict__ a, const float* __restrict__ b,
                   const float* __restrict__ gamma, const float* __restrict__ beta,
                   float eps, float* __restrict__ out,
                   __nv_bfloat16* __restrict__ th, __nv_bfloat16* __restrict__ tl)
{
    long r = blockIdx.x;
    int c = threadIdx.x;
    int w = c >> 5, lane = c & 31;
    float vv = a[r * HH + c] + b[r * HH + c];
    float s = vv, s2 = vv * vv;
#pragma unroll
    for (int o = 16; o; o >>= 1) {
        s  += __shfl_xor_sync(0xFFFFFFFFu, s,  o);
        s2 += __shfl_xor_sync(0xFFFFFFFFu, s2, o);
    }
    __shared__ float rs[8], rs2[8];
    if (lane == 0) { rs[w] = s; rs2[w] = s2; }
    __syncthreads();
    float ts = 0.f, ts2 = 0.f;
#pragma unroll
    for (int i = 0; i < 8; i++) { ts += rs[i]; ts2 += rs2[i]; }
    float mean = ts * (1.0f / HH);
    float var  = ts2 * (1.0f / HH) - mean * mean;
    float inv  = rsqrtf(var + eps);
    float val = (vv - mean) * inv * gamma[c] + beta[c];
    out[r * HH + c] = val;
    if (th) {
        __nv_bfloat16 hb, lb;
        hilo(val, hb, lb);
        th[(size_t)r * HH + c] = hb;
        tl[(size_t)r * HH + c] = lb;
    }
}

// ---------------------------------------------------------------------------
// gating scalar + readout
// ---------------------------------------------------------------------------
__global__ __launch_bounds__(256)
void rowdot_kernel(const float* __restrict__ t, const float* __restrict__ w2,
                   const float* __restrict__ b2, float* __restrict__ gs)
{
    int w = threadIdx.x >> 5, lane = threadIdx.x & 31;
    long r = (long)blockIdx.x * 8 + w;
    float s = 0.f;
    for (int c = lane; c < HH; c += 32) s += t[r * HH + c] * w2[c];
#pragma unroll
    for (int o = 16; o; o >>= 1) s += __shfl_xor_sync(0xFFFFFFFFu, s, o);
    if (lane == 0) gs[r] = s + b2[0];
}

__global__ __launch_bounds__(256)
void readout_kernel(const float* __restrict__ x, const float* __restrict__ gs,
                    float* __restrict__ out)
{
    int g = blockIdx.x, tid = threadIdx.x;
    __shared__ float p[NPG];
    if (tid < NPG) p[tid] = gs[g * NPG + tid];
    __syncthreads();
    if (tid == 0) {
        float mx = -1e30f;
        for (int i = 0; i < NPG; i++) mx = fmaxf(mx, p[i]);
        float sm = 0.f;
        for (int i = 0; i < NPG; i++) { p[i] = expf(p[i] - mx); sm += p[i]; }
        float inv = 1.0f / sm;
        for (int i = 0; i < NPG; i++) p[i] *= inv;
    }
    __syncthreads();
    float acc = 0.f;
    long gbase = (long)g * NPG * HH;
    for (int n = 0; n < NPG; n++)
        acc += p[n] * x[gbase + (long)n * HH + tid];
    out[(long)g * HH + tid] = acc;
}

// ---------------------------------------------------------------------------
// launch
// ---------------------------------------------------------------------------
extern "C" void kernel_launch(void* const* d_in, const int* in_sizes, int n_in,
                              void* d_out, int out_size)
{
    const float* node_feats = (const float*)d_in[0];
    const float* edge_feats = (const float*)d_in[1];
    const int*   dst        = (const int*)  d_in[3];
    const float* Wn      = (const float*)d_in[4];
    const float* bn      = (const float*)d_in[5];
    const float* We      = (const float*)d_in[6];
    const float* be      = (const float*)d_in[7];
    const float* gat_W   = (const float*)d_in[8];
    const float* gat_a   = (const float*)d_in[9];
    const float* gat_lng = (const float*)d_in[10];
    const float* gat_lnb = (const float*)d_in[11];
    const float* Wq      = (const float*)d_in[12];
    const float* Wk      = (const float*)d_in[13];
    const float* Wv      = (const float*)d_in[14];
    const float* att_lng = (const float*)d_in[15];
    const float* att_lnb = (const float*)d_in[16];
    const float* ff_W1   = (const float*)d_in[17];
    const float* ff_b1   = (const float*)d_in[18];
    const float* ff_W2   = (const float*)d_in[19];
    const float* ff_b2   = (const float*)d_in[20];
    const float* ff_lng  = (const float*)d_in[21];
    const float* ff_lnb  = (const float*)d_in[22];
    const float* gW1     = (const float*)d_in[23];
    const float* gb1     = (const float*)d_in[24];
    const float* gW2     = (const float*)d_in[25];
    const float* gb2     = (const float*)d_in[26];

    float *h, *m, *qkv, *att, *x, *elog, *we, *ce, *gs, *aip, *ajp;
    cudaGetSymbolAddress((void**)&h,    gbuf_h);
    cudaGetSymbolAddress((void**)&m,    gbuf_m);
    cudaGetSymbolAddress((void**)&qkv,  gbuf_qkv);
    cudaGetSymbolAddress((void**)&att,  gbuf_att);
    cudaGetSymbolAddress((void**)&x,    gbuf_x);
    cudaGetSymbolAddress((void**)&elog, gbuf_elog);
    cudaGetSymbolAddress((void**)&we,   gbuf_we);
    cudaGetSymbolAddress((void**)&ce,   gbuf_ce);
    cudaGetSymbolAddress((void**)&gs,   gbuf_gs);
    cudaGetSymbolAddress((void**)&aip,  gbuf_aip);
    cudaGetSymbolAddress((void**)&ajp,  gbuf_ajp);

    __nv_bfloat16 *nfh, *nfl, *hh, *hl, *xh, *xl, *h2h, *h2l, *y1h, *y1l;
    __nv_bfloat16 *wnh, *wnl, *gath, *gatl, *wqkvh, *wqkvl, *w1h, *w1l, *w2h, *w2l, *gw1h, *gw1l;
    cudaGetSymbolAddress((void**)&nfh,   p_nf_h);   cudaGetSymbolAddress((void**)&nfl,   p_nf_l);
    cudaGetSymbolAddress((void**)&hh,    p_h_h);    cudaGetSymbolAddress((void**)&hl,    p_h_l);
    cudaGetSymbolAddress((void**)&xh,    p_x_h);    cudaGetSymbolAddress((void**)&xl,    p_x_l);
    cudaGetSymbolAddress((void**)&h2h,   p_h2_h);   cudaGetSymbolAddress((void**)&h2l,   p_h2_l);
    cudaGetSymbolAddress((void**)&y1h,   p_y1_h);   cudaGetSymbolAddress((void**)&y1l,   p_y1_l);
    cudaGetSymbolAddress((void**)&wnh,   p_wn_h);   cudaGetSymbolAddress((void**)&wnl,   p_wn_l);
    cudaGetSymbolAddress((void**)&gath,  p_gat_h);  cudaGetSymbolAddress((void**)&gatl,  p_gat_l);
    cudaGetSymbolAddress((void**)&wqkvh, p_wqkv_h); cudaGetSymbolAddress((void**)&wqkvl, p_wqkv_l);
    cudaGetSymbolAddress((void**)&w1h,   p_w1_h);   cudaGetSymbolAddress((void**)&w1l,   p_w1_l);
    cudaGetSymbolAddress((void**)&w2h,   p_w2_h);   cudaGetSymbolAddress((void**)&w2l,   p_w2_l);
    cudaGetSymbolAddress((void**)&gw1h,  p_gw1_h);  cudaGetSymbolAddress((void**)&gw1l,  p_gw1_l);

    cudaFuncSetAttribute((const void*)mma_gemm<0, true,  true,  false>, cudaFuncAttributeMaxDynamicSharedMemorySize, MG_SMEM);
    cudaFuncSetAttribute((const void*)mma_gemm<0, true,  false, true >, cudaFuncAttributeMaxDynamicSharedMemorySize, MG_SMEM);
    cudaFuncSetAttribute((const void*)mma_gemm<0, true,  false, false>, cudaFuncAttributeMaxDynamicSharedMemorySize, MG_SMEM);
    cudaFuncSetAttribute((const void*)mma_gemm<1, false, true,  false>, cudaFuncAttributeMaxDynamicSharedMemorySize, MG_SMEM);
    cudaFuncSetAttribute((const void*)mma_gemm<2, true,  false, false>, cudaFuncAttributeMaxDynamicSharedMemorySize, MG_SMEM);

    dim3 blk(256);

    prep_kernel<<<1, 160>>>(We, be, gat_a, we, ce);
    edge_logit_kernel<<<EE / 256, blk>>>(edge_feats, we, ce, elog);

    // fused weight conversions (1 launch)
    WTab tab;
    tab.e[0]  = { Wn,                wnh,               wnl,               64,  256 };
    tab.e[1]  = { gat_W + 0 * 65536, gath + 0 * 65536,  gatl + 0 * 65536,  256, 256 };
    tab.e[2]  = { gat_W + 1 * 65536, gath + 1 * 65536,  gatl + 1 * 65536,  256, 256 };
    tab.e[3]  = { gat_W + 2 * 65536, gath + 2 * 65536,  gatl + 2 * 65536,  256, 256 };
    tab.e[4]  = { gat_W + 3 * 65536, gath + 3 * 65536,  gatl + 3 * 65536,  256, 256 };
    tab.e[5]  = { Wq,                wqkvh,             wqkvl,             256, 256 };
    tab.e[6]  = { Wk,                wqkvh + 256 * 256, wqkvl + 256 * 256, 256, 256 };
    tab.e[7]  = { Wv,                wqkvh + 512 * 256, wqkvl + 512 * 256, 256, 256 };
    tab.e[8]  = { ff_W1,             w1h,               w1l,               256, 512 };
    tab.e[9]  = { ff_W2,             w2h,               w2l,               512, 256 };
    tab.e[10] = { gW1,               gw1h,              gw1l,              256, 256 };
    conv_weights<<<dim3(64, 11), blk>>>(tab);
    to_hiloA<<<(NN * 64 + 255) / 256, blk>>>(node_feats, (long)NN * 64, nfh, nfl);

    dim3 g1(2, NN / 128);    // Nout 256
    dim3 g2(4, NN / 128);    // Nout 512
    dim3 g3(6, NN / 128);    // Nout 768 (QKV)

    // input projection: h = nf @ Wn + bn
    mma_gemm<0, true, true, false><<<g1, blk, MG_SMEM>>>(2, 64, nfh, nfl, wnh, wnl,
        bn, 256, h, hh, hl, nullptr, nullptr, nullptr);

    // GAT layers
    for (int l = 0; l < LL; l++) {
        mma_gemm<0, true, false, true><<<g1, blk, MG_SMEM>>>(8, 256, hh, hl,
            gath + (size_t)l * 65536, gatl + (size_t)l * 65536,
            nullptr, 256, m, nullptr, nullptr, gat_a + l * 768, aip, ajp);
        gat_kernel<<<BB, blk>>>(m, h, elog + (long)l * EE, dst, aip, ajp,
                                gat_lng + l * HH, gat_lnb + l * HH, hh, hl);
    }

    // global attention (fused QKV)
    mma_gemm<0, true, false, false><<<g3, blk, MG_SMEM>>>(8, 256, hh, hl, wqkvh, wqkvl,
        nullptr, 768, qkv, nullptr, nullptr, nullptr, nullptr, nullptr);
    attn_kernel<<<dim3(BB, HEADS), 64>>>(qkv, att);
    add_ln_kernel<<<NN, blk>>>(att, h, att_lng, att_lnb, 1e-6f, x, xh, xl);

    // feed-forward
    mma_gemm<1, false, true, false><<<g2, blk, MG_SMEM>>>(8, 256, xh, xl, w1h, w1l,
        ff_b1, 512, nullptr, y1h, y1l, nullptr, nullptr, nullptr);
    mma_gemm<0, true, false, false><<<g1, blk, MG_SMEM>>>(16, 512, y1h, y1l, w2h, w2l,
        ff_b2, 256, m, nullptr, nullptr, nullptr, nullptr, nullptr);
    add_ln_kernel<<<NN, blk>>>(x, m, ff_lng, ff_lnb, 1e-6f, h, h2h, h2l);

    // gating readout
    mma_gemm<2, true, false, false><<<g1, blk, MG_SMEM>>>(8, 256, h2h, h2l, gw1h, gw1l,
        gb1, 256, m, nullptr, nullptr, nullptr, nullptr, nullptr);
    rowdot_kernel<<<NN / 8, blk>>>(m, gW2, gb2, gs);
    readout_kernel<<<BB, blk>>>(h, gs, (float*)d_out);
}